// round 8
// baseline (speedup 1.0000x reference)
#include <cuda_runtime.h>
#include <cuda.h>
#include <cuda_fp16.h>
#include <math.h>
#include <stdint.h>

#define BATCH 4096
#define DDIM  1024
#define NSTAGE 3
#define STAGE_FULL 49152u           // A 16K + B_op0 16K + B_op1 16K
#define STAGE_HALF 32768u           // A 16K + B_op0 16K (last pass, single op)
#define MIX_OFF   149504u           // 2048 + 3*49152
#define DYN_SMEM  215040u           // MIX_OFF + 64KB mix

// ------------------------- device scratch (no cudaMalloc) -------------------
__device__ __half g_ws[73400320];     // [14*5][n=1024][k=1024]
__device__ __half g_wb[41943040];     // [4*5][n=1024][k=2048]
__device__ __half g_x[5][4194304];    // s0,s1,n0,n1,n2: [4096][1024]

// ------------------------------ PTX helpers ---------------------------------
__device__ __forceinline__ uint32_t smem_u32(const void* p) {
    uint32_t a;
    asm("{ .reg .u64 t; cvta.to.shared.u64 t, %1; cvt.u32.u64 %0, t; }"
        : "=r"(a) : "l"(p));
    return a;
}

#define MBAR_INIT(addr, cnt) \
    asm volatile("mbarrier.init.shared.b64 [%0], %1;" :: "r"(addr), "r"((uint32_t)(cnt)) : "memory")
#define MBAR_EXPECT_TX(addr, bytes) \
    asm volatile("mbarrier.arrive.expect_tx.shared.b64 _, [%0], %1;" :: "r"(addr), "r"((uint32_t)(bytes)) : "memory")
#define MBAR_ARRIVE(addr) \
    asm volatile("mbarrier.arrive.shared.b64 _, [%0];" :: "r"(addr) : "memory")
#define MBAR_WAIT(addr, ph) do {                                              \
    asm volatile(                                                             \
        "{\n\t.reg .pred P1;\n\t"                                             \
        "WL_%=:\n\t"                                                          \
        "mbarrier.try_wait.parity.acquire.cta.shared::cta.b64 P1, [%0], %1, 0x989680;\n\t" \
        "@P1 bra.uni WD_%=;\n\t"                                              \
        "bra.uni WL_%=;\n\t"                                                  \
        "WD_%=:\n\t}"                                                         \
        :: "r"((uint32_t)(addr)), "r"((uint32_t)(ph)) : "memory");            \
} while (0)

#define TMA2D(smaddr, map, cx, cy, mbar) \
    asm volatile("cp.async.bulk.tensor.2d.shared::cta.global.tile.mbarrier::complete_tx::bytes " \
                 "[%0], [%1, {%2, %3}], [%4];" \
                 :: "r"(smaddr), "l"(map), "r"(cx), "r"(cy), "r"(mbar) : "memory")

__device__ __forceinline__ void ldsm4(uint32_t addr, uint32_t r[4]) {
    asm volatile("ldmatrix.sync.aligned.m8n8.x4.shared.b16 {%0,%1,%2,%3}, [%4];"
        : "=r"(r[0]), "=r"(r[1]), "=r"(r[2]), "=r"(r[3]) : "r"(addr));
}

__device__ __forceinline__ void mma16816(float c[4], const uint32_t a[4],
                                         uint32_t b0, uint32_t b1) {
    asm volatile("mma.sync.aligned.m16n8k16.row.col.f32.f16.f16.f32 "
        "{%0,%1,%2,%3}, {%4,%5,%6,%7}, {%8,%9}, {%0,%1,%2,%3};"
        : "+f"(c[0]), "+f"(c[1]), "+f"(c[2]), "+f"(c[3])
        : "r"(a[0]), "r"(a[1]), "r"(a[2]), "r"(a[3]), "r"(b0), "r"(b1));
}

// ------------------------------- structs ------------------------------------
struct EdgeInfo {
    int a0, a1;        // g_x index for k<1024 / k>=1024
    int b_is_wb;       // 0: g_ws, 1: g_wb
    int b_row_base;    // tensor-local row base (idx*5*1024)
    int K;             // 1024 or 2048
    int layer;         // global layer index
};
struct NodeP {
    CUtensorMap a_map[5];
    CUtensorMap ws_map, wb_map;
    EdgeInfo e[6];
    int n_edges;
    int node_out_idx;  // 2..4 -> g_x dest, -1 -> final fp32 out
};

// --------------------------- conversion kernels -----------------------------
__global__ void cvt_in(const float* __restrict__ s, int idx) {
    int i = blockIdx.x * 256 + threadIdx.x;
    g_x[idx][i] = __float2half(s[i]);
}

// src: [Z][K][1024] fp32 -> dst: [Z][1024][K] fp16 (transpose)
__global__ void cvt_w(const float* __restrict__ src,
                      __half* __restrict__ dst, int K) {
    __shared__ float t[32][33];
    const int z = blockIdx.z;
    const int k0 = blockIdx.x * 32, n0 = blockIdx.y * 32;
    const int tx = threadIdx.x, ty = threadIdx.y;   // (32, 8)
    const float* s = src + (size_t)z * K * 1024;
    #pragma unroll
    for (int r = 0; r < 4; r++)
        t[ty + 8 * r][tx] = s[(size_t)(k0 + ty + 8 * r) * 1024 + n0 + tx];
    __syncthreads();
    const size_t dbase = (size_t)z * 1024 * K;
    #pragma unroll
    for (int r = 0; r < 4; r++) {
        const int n = n0 + ty + 8 * r, k = k0 + tx;
        dst[dbase + (size_t)n * K + k] = __float2half(t[tx][ty + 8 * r]);
    }
}

// ------------------------------ GEMM kernel ---------------------------------
// 3 passes per edge: ops (0,1), (2,3), (4). A fragments shared by the op pair.
__global__ void __launch_bounds__(256, 1)
gemm_node(const __grid_constant__ NodeP P,
          const float* __restrict__ geno,
          const float* __restrict__ bsv,
          float* __restrict__ outp)
{
    extern __shared__ char dynsmem[];
    const uint32_t sb = smem_u32(dynsmem);
    const uint32_t tile0 = sb + 2048u;
    float* sbias = (float*)(dynsmem + 256);           // [2][128]
    float* mixs  = (float*)(dynsmem + MIX_OFF);       // [64][256]
    const int tid = (int)threadIdx.x;
    const int lane = tid & 31, wid = tid >> 5;
    const int bm = blockIdx.y * 128, bn = blockIdx.x * 128;
    const int mbase = (wid >> 2) * 64;   // 2 m-warps
    const int nbase = (wid & 3) * 32;    // 4 n-warps

    if (tid == 0) {
        #pragma unroll
        for (int s = 0; s < NSTAGE; s++) {
            MBAR_INIT(sb + s * 8, 1);          // full: tx-based
            MBAR_INIT(sb + 64 + s * 8, 8);     // empty: one arrive per warp
        }
    }
    #pragma unroll
    for (int i = 0; i < 64; i++) mixs[i * 256 + tid] = 0.0f;
    __syncthreads();

    // per-thread ldmatrix row offsets (rows of 128B = 64 fp16)
    uint32_t aOff[4]; int aSw[4];
    #pragma unroll
    for (int mb = 0; mb < 4; mb++) {
        const int r = mbase + mb * 16 + (lane & 15);
        aOff[mb] = (uint32_t)r * 128u; aSw[mb] = r & 7;
    }
    uint32_t bOff[2]; int bSw[2];
    #pragma unroll
    for (int nb = 0; nb < 2; nb++) {
        const int r = nbase + nb * 16 + (lane & 7) + ((lane >> 3) & 1) * 8;
        bOff[nb] = (uint32_t)r * 128u; bSw[nb] = r & 7;
    }
    const int hi16 = lane >> 4;

    // producer iterator state (tid 0 only)
    int pe = 0, pp = 0, pkt = 0;

    auto issue = [&](int t) {
        if (pe >= P.n_edges) return;
        const EdgeInfo ei = P.e[pe];
        const int s = t % NSTAGE;
        if (t >= NSTAGE) {
            const int ph = ((t / NSTAGE) + 1) & 1;
            MBAR_WAIT(sb + 64 + s * 8, ph);
        }
        const bool two = (pp < 2);
        const uint32_t st = tile0 + (uint32_t)s * STAGE_FULL;
        MBAR_EXPECT_TX(sb + s * 8, two ? STAGE_FULL : STAGE_HALF);
        const int kg = pkt * 64;
        int ka = kg;
        const CUtensorMap* A = &P.a_map[ei.a0];
        if (kg >= 1024) { A = &P.a_map[ei.a1]; ka = kg - 1024; }
        const CUtensorMap* B = ei.b_is_wb ? &P.wb_map : &P.ws_map;
        const int by = ei.b_row_base + pp * 2 * 1024 + bn;
        TMA2D(st,           A, ka, bm, sb + s * 8);
        TMA2D(st + 16384u,  B, kg, by, sb + s * 8);
        if (two) TMA2D(st + 32768u, B, kg, by + 1024, sb + s * 8);
        if (++pkt == ei.K / 64) { pkt = 0; if (++pp == 3) { pp = 0; ++pe; } }
    };

    if (tid == 0) {
        #pragma unroll
        for (int s = 0; s < NSTAGE; s++) issue(s);
    }

    int t = 0;
    for (int e = 0; e < P.n_edges; e++) {
        const int layer = P.e[e].layer;
        const int nch = P.e[e].K / 64;

        for (int pass = 0; pass < 3; pass++) {
            const bool two = (pass < 2);
            float c0[4][4][4], c1[4][4][4];
            #pragma unroll
            for (int i = 0; i < 4; i++)
                #pragma unroll
                for (int j = 0; j < 4; j++)
                    #pragma unroll
                    for (int r = 0; r < 4; r++) { c0[i][j][r] = 0.0f; c1[i][j][r] = 0.0f; }

            for (int kt = 0; kt < nch; kt++) {
                const int s = t % NSTAGE;
                MBAR_WAIT(sb + s * 8, (t / NSTAGE) & 1);
                const uint32_t st = tile0 + (uint32_t)s * STAGE_FULL;

                #pragma unroll
                for (int ks = 0; ks < 4; ks++) {
                    uint32_t af[4][4], b0f[2][4], b1f[2][4];
                    #pragma unroll
                    for (int mb = 0; mb < 4; mb++) {
                        const uint32_t co =
                            (uint32_t)(((ks * 2 + hi16) ^ aSw[mb]) * 16);
                        ldsm4(st + aOff[mb] + co, af[mb]);
                    }
                    #pragma unroll
                    for (int nb = 0; nb < 2; nb++) {
                        const uint32_t co =
                            (uint32_t)(((ks * 2 + hi16) ^ bSw[nb]) * 16);
                        ldsm4(st + 16384u + bOff[nb] + co, b0f[nb]);
                        if (two) ldsm4(st + 32768u + bOff[nb] + co, b1f[nb]);
                    }
                    #pragma unroll
                    for (int mb = 0; mb < 4; mb++)
                        #pragma unroll
                        for (int n8 = 0; n8 < 4; n8++) {
                            const int nb = n8 >> 1, hf = n8 & 1;
                            mma16816(c0[mb][n8], af[mb], b0f[nb][hf], b0f[nb][hf + 2]);
                            if (two)
                                mma16816(c1[mb][n8], af[mb], b1f[nb][hf], b1f[nb][hf + 2]);
                        }
                }
                if (lane == 0) MBAR_ARRIVE(sb + 64 + s * 8);
                if (tid == 0) issue(t + NSTAGE);
                t++;
            }

            // ------- epilogue: mix += w0*act0(h0) [+ w1*act1(h1)] -------
            const int opa = pass * 2;
            const float w0 = __ldg(&geno[layer * 5 + opa]);
            const float w1 = two ? __ldg(&geno[layer * 5 + opa + 1]) : 0.0f;
            __syncthreads();
            if (tid < 128) {
                sbias[tid] = __ldg(&bsv[((size_t)layer * 5 + opa) * 1024 + bn + tid]);
                sbias[128 + tid] = two
                    ? __ldg(&bsv[((size_t)layer * 5 + opa + 1) * 1024 + bn + tid]) : 0.0f;
            }
            __syncthreads();

            #pragma unroll
            for (int mb = 0; mb < 4; mb++)
                #pragma unroll
                for (int n8 = 0; n8 < 4; n8++)
                    #pragma unroll
                    for (int r = 0; r < 4; r++) {
                        const int n = nbase + n8 * 8 + (lane & 3) * 2 + (r & 1);
                        const int idx = (mb * 4 + n8) * 4 + r;
                        const float h0 = c0[mb][n8][r] + sbias[n];
                        const float h1 = c1[mb][n8][r] + sbias[128 + n];
                        float add;
                        if (pass == 0)
                            add = w0 * h0 + w1 * fmaxf(h1, 0.0f);
                        else if (pass == 1)
                            add = w0 * (__fdividef(2.0f, 1.0f + __expf(-2.0f * h0)) - 1.0f)
                                + w1 * __fdividef(1.0f, 1.0f + __expf(-h1));
                        else
                            add = w0 * (h0 > 0.0f ? h0 : 0.2f * h0);
                        mixs[idx * 256 + tid] += add;
                    }
        }
    }

    // ------- write node output -------
    if (P.node_out_idx >= 0) {
        __half* dh = g_x[P.node_out_idx];
        #pragma unroll
        for (int mb = 0; mb < 4; mb++)
            #pragma unroll
            for (int n8 = 0; n8 < 4; n8++)
                #pragma unroll
                for (int r = 0; r < 4; r++) {
                    const int m = bm + mbase + mb * 16 + (lane >> 2) + ((r >> 1) & 1) * 8;
                    const int n = bn + nbase + n8 * 8 + (lane & 3) * 2 + (r & 1);
                    const int idx = (mb * 4 + n8) * 4 + r;
                    dh[(size_t)m * 1024 + n] = __float2half(mixs[idx * 256 + tid]);
                }
    } else {
        #pragma unroll
        for (int mb = 0; mb < 4; mb++)
            #pragma unroll
            for (int n8 = 0; n8 < 4; n8++)
                #pragma unroll
                for (int r = 0; r < 4; r++) {
                    const int m = bm + mbase + mb * 16 + (lane >> 2) + ((r >> 1) & 1) * 8;
                    const int n = bn + nbase + n8 * 8 + (lane & 3) * 2 + (r & 1);
                    const int idx = (mb * 4 + n8) * 4 + r;
                    outp[(size_t)m * 1024 + n] = mixs[idx * 256 + tid];
                }
    }
}

// --------------------------------- host -------------------------------------
typedef CUresult (*EncodeFn)(CUtensorMap*, CUtensorMapDataType, cuuint32_t, void*,
                             const cuuint64_t*, const cuuint64_t*, const cuuint32_t*,
                             const cuuint32_t*, CUtensorMapInterleave, CUtensorMapSwizzle,
                             CUtensorMapL2promotion, CUtensorMapFloatOOBfill);

static void make2d(EncodeFn enc, CUtensorMap* out, void* base,
                   uint64_t dim0, uint64_t dim1, uint64_t stride_b, uint32_t boxh) {
    cuuint64_t dims[2]    = {dim0, dim1};
    cuuint64_t strides[1] = {stride_b};
    cuuint32_t box[2]     = {64u, boxh};
    cuuint32_t es[2]      = {1u, 1u};
    enc(out, CU_TENSOR_MAP_DATA_TYPE_FLOAT16, 2, base, dims, strides, box, es,
        CU_TENSOR_MAP_INTERLEAVE_NONE, CU_TENSOR_MAP_SWIZZLE_128B,
        CU_TENSOR_MAP_L2_PROMOTION_L2_128B, CU_TENSOR_MAP_FLOAT_OOB_FILL_NONE);
}

extern "C" void kernel_launch(void* const* d_in, const int* in_sizes, int n_in,
                              void* d_out, int out_size)
{
    const float *s0 = nullptr, *s1 = nullptr, *geno = nullptr;
    const float *Ws = nullptr, *Wb = nullptr, *bsv = nullptr;
    for (int i = 0; i < n_in; i++) {
        const long sz = (long)in_sizes[i];
        const float* p = (const float*)d_in[i];
        if      (sz == (long)BATCH * DDIM)   { if (!s0) s0 = p; else s1 = p; }
        else if (sz == 90L)                    geno = p;
        else if (sz == 73400320L)              Ws = p;
        else if (sz == 41943040L)              Wb = p;
        else if (sz == 92160L)                 bsv = p;
    }

    void *ws, *wb, *x;
    cudaGetSymbolAddress(&ws, g_ws);
    cudaGetSymbolAddress(&wb, g_wb);
    cudaGetSymbolAddress(&x,  g_x);

    void* fp = nullptr;
    cudaDriverEntryPointQueryResult qres;
    cudaGetDriverEntryPointByVersion("cuTensorMapEncodeTiled", &fp, 12000,
                                     cudaEnableDefault, &qres);
    EncodeFn enc = (EncodeFn)fp;

    NodeP base;
    for (int i = 0; i < 5; i++)
        make2d(enc, &base.a_map[i], (char*)x + (size_t)i * 4194304 * 2, 1024, 4096, 2048, 128);
    make2d(enc, &base.ws_map, ws, 1024, 71680, 2048, 128);
    make2d(enc, &base.wb_map, wb, 2048, 20480, 4096, 128);

    // conversions
    cvt_in<<<16384, 256>>>(s0, 0);
    cvt_in<<<16384, 256>>>(s1, 1);
    dim3 tb(32, 8);
    cvt_w<<<dim3(32, 32, 70), tb>>>(Ws, (__half*)ws, 1024);
    cvt_w<<<dim3(64, 32, 20), tb>>>(Wb, (__half*)wb, 2048);

    cudaFuncSetAttribute(gemm_node, cudaFuncAttributeMaxDynamicSharedMemorySize, DYN_SMEM);

    dim3 grid(8, 32), blk(256);
    int si = 0, bi = 0, offset = 0;
    for (int node = 0; node < 4; node++) {
        NodeP P = base;
        P.n_edges = node + 3;
        for (int j = 0; j < node + 3; j++) {
            EdgeInfo& e = P.e[j];
            e.layer = offset + j;
            if (j == 2) {
                e.b_is_wb = 1; e.b_row_base = bi * 5 * 1024; bi++;
                e.K = 2048; e.a0 = 0; e.a1 = 1;
            } else {
                e.b_is_wb = 0; e.b_row_base = si * 5 * 1024; si++;
                e.K = 1024;
                e.a0 = e.a1 = (j < 2) ? j : (j - 1);
            }
        }
        P.node_out_idx = (node < 3) ? (2 + node) : -1;
        gemm_node<<<grid, blk, DYN_SMEM>>>(P, geno, bsv, (float*)d_out);
        offset += node + 3;
    }
}

// round 9
// speedup vs baseline: 1.1453x; 1.1453x over previous
#include <cuda_runtime.h>
#include <cuda.h>
#include <cuda_fp16.h>
#include <math.h>
#include <stdint.h>

#define BATCH 4096
#define DDIM  1024
#define NSTAGE 3
#define STAGE  32768u
#define DYN_SMEM (2048u + NSTAGE * STAGE)   // 100352 bytes -> 2 CTAs/SM

// ------------------------- device scratch (no cudaMalloc) -------------------
__device__ __half g_ws[73400320];     // [14*5][n=1024][k=1024]
__device__ __half g_wb[41943040];     // [4*5][n=1024][k=2048]
__device__ __half g_x[5][4194304];    // s0,s1,n0,n1,n2: [4096][1024]
__device__ float  g_mix[4194304];     // per-CTA mix accumulator (16MB, L2-resident)

// ------------------------------ PTX helpers ---------------------------------
__device__ __forceinline__ uint32_t smem_u32(const void* p) {
    uint32_t a;
    asm("{ .reg .u64 t; cvta.to.shared.u64 t, %1; cvt.u32.u64 %0, t; }"
        : "=r"(a) : "l"(p));
    return a;
}

#define MBAR_INIT(addr, cnt) \
    asm volatile("mbarrier.init.shared.b64 [%0], %1;" :: "r"(addr), "r"((uint32_t)(cnt)) : "memory")
#define MBAR_EXPECT_TX(addr, bytes) \
    asm volatile("mbarrier.arrive.expect_tx.shared.b64 _, [%0], %1;" :: "r"(addr), "r"((uint32_t)(bytes)) : "memory")
#define MBAR_ARRIVE(addr) \
    asm volatile("mbarrier.arrive.shared.b64 _, [%0];" :: "r"(addr) : "memory")
#define MBAR_WAIT(addr, ph) do {                                              \
    asm volatile(                                                             \
        "{\n\t.reg .pred P1;\n\t"                                             \
        "WL_%=:\n\t"                                                          \
        "mbarrier.try_wait.parity.acquire.cta.shared::cta.b64 P1, [%0], %1, 0x989680;\n\t" \
        "@P1 bra.uni WD_%=;\n\t"                                              \
        "bra.uni WL_%=;\n\t"                                                  \
        "WD_%=:\n\t}"                                                         \
        :: "r"((uint32_t)(addr)), "r"((uint32_t)(ph)) : "memory");            \
} while (0)

#define TMA2D(smaddr, map, cx, cy, mbar) \
    asm volatile("cp.async.bulk.tensor.2d.shared::cta.global.tile.mbarrier::complete_tx::bytes " \
                 "[%0], [%1, {%2, %3}], [%4];" \
                 :: "r"(smaddr), "l"(map), "r"(cx), "r"(cy), "r"(mbar) : "memory")

__device__ __forceinline__ void ldsm4(uint32_t addr, uint32_t r[4]) {
    asm volatile("ldmatrix.sync.aligned.m8n8.x4.shared.b16 {%0,%1,%2,%3}, [%4];"
        : "=r"(r[0]), "=r"(r[1]), "=r"(r[2]), "=r"(r[3]) : "r"(addr));
}

__device__ __forceinline__ void mma16816(float c[4], const uint32_t a[4],
                                         uint32_t b0, uint32_t b1) {
    asm volatile("mma.sync.aligned.m16n8k16.row.col.f32.f16.f16.f32 "
        "{%0,%1,%2,%3}, {%4,%5,%6,%7}, {%8,%9}, {%0,%1,%2,%3};"
        : "+f"(c[0]), "+f"(c[1]), "+f"(c[2]), "+f"(c[3])
        : "r"(a[0]), "r"(a[1]), "r"(a[2]), "r"(a[3]), "r"(b0), "r"(b1));
}

// ------------------------------- structs ------------------------------------
struct EdgeInfo {
    int a0, a1;        // g_x index for k<1024 / k>=1024
    int b_is_wb;       // 0: g_ws, 1: g_wb
    int b_row_base;    // tensor-local row base (idx*5*1024)
    int K;             // 1024 or 2048
    int layer;         // global layer index
};
struct NodeP {
    CUtensorMap a_map[5];
    CUtensorMap ws_map, wb_map;
    EdgeInfo e[6];
    int n_edges;
    int node_out_idx;  // 2..4 -> g_x dest, -1 -> final fp32 out
};

// --------------------------- conversion kernels -----------------------------
__global__ void cvt_in(const float* __restrict__ s, int idx) {
    int i = blockIdx.x * 256 + threadIdx.x;
    g_x[idx][i] = __float2half(s[i]);
}

// src: [Z][K][1024] fp32 -> dst: [Z][1024][K] fp16 (transpose)
__global__ void cvt_w(const float* __restrict__ src,
                      __half* __restrict__ dst, int K) {
    __shared__ float t[32][33];
    const int z = blockIdx.z;
    const int k0 = blockIdx.x * 32, n0 = blockIdx.y * 32;
    const int tx = threadIdx.x, ty = threadIdx.y;   // (32, 8)
    const float* s = src + (size_t)z * K * 1024;
    #pragma unroll
    for (int r = 0; r < 4; r++)
        t[ty + 8 * r][tx] = s[(size_t)(k0 + ty + 8 * r) * 1024 + n0 + tx];
    __syncthreads();
    const size_t dbase = (size_t)z * 1024 * K;
    #pragma unroll
    for (int r = 0; r < 4; r++) {
        const int n = n0 + ty + 8 * r, k = k0 + tx;
        dst[dbase + (size_t)n * K + k] = __float2half(t[tx][ty + 8 * r]);
    }
}

// ------------------------------ GEMM kernel ---------------------------------
__global__ void __launch_bounds__(256, 2)
gemm_node(const __grid_constant__ NodeP P,
          const float* __restrict__ geno,
          const float* __restrict__ bsv,
          float* __restrict__ outp)
{
    extern __shared__ char dynsmem[];
    const uint32_t sb = smem_u32(dynsmem);
    const uint32_t tile0 = sb + 2048u;
    float* sbias = (float*)(dynsmem + 256);
    const int tid = (int)threadIdx.x;
    const int lane = tid & 31, wid = tid >> 5;
    const int bm = blockIdx.y * 128, bn = blockIdx.x * 128;
    const int mbase = (wid >> 2) * 64;   // 2 m-warps
    const int nbase = (wid & 3) * 32;    // 4 n-warps
    float* mixg = g_mix + ((size_t)(blockIdx.y * gridDim.x + blockIdx.x) * 16384);

    if (tid == 0) {
        #pragma unroll
        for (int s = 0; s < NSTAGE; s++) {
            MBAR_INIT(sb + s * 8, 1);          // full: tx-based
            MBAR_INIT(sb + 64 + s * 8, 8);     // empty: one arrive per warp
        }
    }
    __syncthreads();

    // per-thread ldmatrix row offsets (rows of 128B = 64 fp16)
    uint32_t aOff[4]; int aSw[4];
    #pragma unroll
    for (int mb = 0; mb < 4; mb++) {
        const int r = mbase + mb * 16 + (lane & 15);
        aOff[mb] = (uint32_t)r * 128u; aSw[mb] = r & 7;
    }
    uint32_t bOff[2]; int bSw[2];
    #pragma unroll
    for (int nb = 0; nb < 2; nb++) {
        const int r = nbase + nb * 16 + (lane & 7) + ((lane >> 3) & 1) * 8;
        bOff[nb] = (uint32_t)r * 128u; bSw[nb] = r & 7;
    }
    const int hi16 = lane >> 4;

    // producer iterator state (tid 0 only)
    int pe = 0, pop = 0, pkt = 0;

    auto issue = [&](int t) {
        if (pe >= P.n_edges) return;
        const EdgeInfo ei = P.e[pe];
        const int s = t % NSTAGE;
        if (t >= NSTAGE) {
            const int ph = ((t / NSTAGE) + 1) & 1;
            MBAR_WAIT(sb + 64 + s * 8, ph);
        }
        const uint32_t st = tile0 + (uint32_t)s * STAGE;
        MBAR_EXPECT_TX(sb + s * 8, STAGE);
        const int kg = pkt * 64;
        int ka = kg;
        const CUtensorMap* A = &P.a_map[ei.a0];
        if (kg >= 1024) { A = &P.a_map[ei.a1]; ka = kg - 1024; }
        const CUtensorMap* B = ei.b_is_wb ? &P.wb_map : &P.ws_map;
        const int by = ei.b_row_base + pop * 1024 + bn;
        TMA2D(st,           A, ka, bm, sb + s * 8);
        TMA2D(st + 16384u,  B, kg, by, sb + s * 8);
        if (++pkt == ei.K / 64) { pkt = 0; if (++pop == 5) { pop = 0; ++pe; } }
    };

    if (tid == 0) {
        #pragma unroll
        for (int s = 0; s < NSTAGE; s++) issue(s);
    }

    int t = 0;
    for (int e = 0; e < P.n_edges; e++) {
        const int layer = P.e[e].layer;
        const int nch = P.e[e].K / 64;

        for (int op = 0; op < 5; op++) {
            float c[4][4][4];
            #pragma unroll
            for (int i = 0; i < 4; i++)
                #pragma unroll
                for (int j = 0; j < 4; j++)
                    #pragma unroll
                    for (int r = 0; r < 4; r++) c[i][j][r] = 0.0f;

            for (int kt = 0; kt < nch; kt++) {
                const int s = t % NSTAGE;
                MBAR_WAIT(sb + s * 8, (t / NSTAGE) & 1);
                const uint32_t st = tile0 + (uint32_t)s * STAGE;

                #pragma unroll
                for (int ks = 0; ks < 4; ks++) {
                    uint32_t bfrag[2][4];
                    #pragma unroll
                    for (int nb = 0; nb < 2; nb++) {
                        const uint32_t co =
                            (uint32_t)(((ks * 2 + hi16) ^ bSw[nb]) * 16);
                        ldsm4(st + 16384u + bOff[nb] + co, bfrag[nb]);
                    }
                    #pragma unroll
                    for (int mb = 0; mb < 4; mb++) {
                        uint32_t afrag[4];
                        const uint32_t co =
                            (uint32_t)(((ks * 2 + hi16) ^ aSw[mb]) * 16);
                        ldsm4(st + aOff[mb] + co, afrag);
                        #pragma unroll
                        for (int n8 = 0; n8 < 4; n8++) {
                            const int nb = n8 >> 1, hf = n8 & 1;
                            mma16816(c[mb][n8], afrag,
                                     bfrag[nb][hf], bfrag[nb][hf + 2]);
                        }
                    }
                }
                if (lane == 0) MBAR_ARRIVE(sb + 64 + s * 8);
                if (tid == 0) issue(t + NSTAGE);
                t++;
            }

            // ------- epilogue: mixg (+)= geno * act(c + bias) -------
            const float wgt = __ldg(&geno[layer * 5 + op]);
            __syncthreads();
            if (tid < 128)
                sbias[tid] = __ldg(&bsv[((size_t)layer * 5 + op) * 1024 + bn + tid]);
            __syncthreads();

            const bool first = (e == 0) && (op == 0);
            const bool last  = (e == P.n_edges - 1) && (op == 4);

            #define MIX_BODY(AEXPR)                                            \
                _Pragma("unroll")                                              \
                for (int mb = 0; mb < 4; mb++)                                 \
                _Pragma("unroll")                                              \
                for (int n8 = 0; n8 < 4; n8++)                                 \
                _Pragma("unroll")                                              \
                for (int r = 0; r < 4; r++) {                                  \
                    const float h = c[mb][n8][r] +                             \
                        sbias[nbase + n8 * 8 + (lane & 3) * 2 + (r & 1)];      \
                    const float v = wgt * (AEXPR);                             \
                    const int idx = ((mb * 4 + n8) * 4 + r) * 256 + tid;       \
                    if (first) mixg[idx] = v;                                  \
                    else if (!last) mixg[idx] += v;                            \
                    else {                                                     \
                        const float tot = mixg[idx] + v;                       \
                        const int m = bm + mbase + mb * 16 + (lane >> 2)       \
                                      + ((r >> 1) & 1) * 8;                    \
                        const int n = bn + nbase + n8 * 8 + (lane & 3) * 2     \
                                      + (r & 1);                               \
                        if (P.node_out_idx >= 0)                               \
                            g_x[P.node_out_idx][(size_t)m * 1024 + n] =        \
                                __float2half(tot);                             \
                        else                                                   \
                            outp[(size_t)m * 1024 + n] = tot;                  \
                    }                                                          \
                }
            switch (op) {
                case 0: MIX_BODY(h); break;
                case 1: MIX_BODY(fmaxf(h, 0.0f)); break;
                case 2: MIX_BODY(__fdividef(2.0f, 1.0f + __expf(-2.0f * h)) - 1.0f); break;
                case 3: MIX_BODY(__fdividef(1.0f, 1.0f + __expf(-h))); break;
                default: MIX_BODY(h > 0.0f ? h : 0.2f * h); break;
            }
            #undef MIX_BODY
        }
    }
}

// --------------------------------- host -------------------------------------
typedef CUresult (*EncodeFn)(CUtensorMap*, CUtensorMapDataType, cuuint32_t, void*,
                             const cuuint64_t*, const cuuint64_t*, const cuuint32_t*,
                             const cuuint32_t*, CUtensorMapInterleave, CUtensorMapSwizzle,
                             CUtensorMapL2promotion, CUtensorMapFloatOOBfill);

static void make2d(EncodeFn enc, CUtensorMap* out, void* base,
                   uint64_t dim0, uint64_t dim1, uint64_t stride_b, uint32_t boxh) {
    cuuint64_t dims[2]    = {dim0, dim1};
    cuuint64_t strides[1] = {stride_b};
    cuuint32_t box[2]     = {64u, boxh};
    cuuint32_t es[2]      = {1u, 1u};
    enc(out, CU_TENSOR_MAP_DATA_TYPE_FLOAT16, 2, base, dims, strides, box, es,
        CU_TENSOR_MAP_INTERLEAVE_NONE, CU_TENSOR_MAP_SWIZZLE_128B,
        CU_TENSOR_MAP_L2_PROMOTION_L2_128B, CU_TENSOR_MAP_FLOAT_OOB_FILL_NONE);
}

extern "C" void kernel_launch(void* const* d_in, const int* in_sizes, int n_in,
                              void* d_out, int out_size)
{
    const float *s0 = nullptr, *s1 = nullptr, *geno = nullptr;
    const float *Ws = nullptr, *Wb = nullptr, *bsv = nullptr;
    for (int i = 0; i < n_in; i++) {
        const long sz = (long)in_sizes[i];
        const float* p = (const float*)d_in[i];
        if      (sz == (long)BATCH * DDIM)   { if (!s0) s0 = p; else s1 = p; }
        else if (sz == 90L)                    geno = p;
        else if (sz == 73400320L)              Ws = p;
        else if (sz == 41943040L)              Wb = p;
        else if (sz == 92160L)                 bsv = p;
    }

    void *ws, *wb, *x;
    cudaGetSymbolAddress(&ws, g_ws);
    cudaGetSymbolAddress(&wb, g_wb);
    cudaGetSymbolAddress(&x,  g_x);

    void* fp = nullptr;
    cudaDriverEntryPointQueryResult qres;
    cudaGetDriverEntryPointByVersion("cuTensorMapEncodeTiled", &fp, 12000,
                                     cudaEnableDefault, &qres);
    EncodeFn enc = (EncodeFn)fp;

    NodeP base;
    for (int i = 0; i < 5; i++)
        make2d(enc, &base.a_map[i], (char*)x + (size_t)i * 4194304 * 2, 1024, 4096, 2048, 128);
    make2d(enc, &base.ws_map, ws, 1024, 71680, 2048, 128);
    make2d(enc, &base.wb_map, wb, 2048, 20480, 4096, 128);

    // conversions
    cvt_in<<<16384, 256>>>(s0, 0);
    cvt_in<<<16384, 256>>>(s1, 1);
    dim3 tb(32, 8);
    cvt_w<<<dim3(32, 32, 70), tb>>>(Ws, (__half*)ws, 1024);
    cvt_w<<<dim3(64, 32, 20), tb>>>(Wb, (__half*)wb, 2048);

    cudaFuncSetAttribute(gemm_node, cudaFuncAttributeMaxDynamicSharedMemorySize, DYN_SMEM);

    dim3 grid(8, 32), blk(256);
    int si = 0, bi = 0, offset = 0;
    for (int node = 0; node < 4; node++) {
        NodeP P = base;
        P.n_edges = node + 3;
        for (int j = 0; j < node + 3; j++) {
            EdgeInfo& e = P.e[j];
            e.layer = offset + j;
            if (j == 2) {
                e.b_is_wb = 1; e.b_row_base = bi * 5 * 1024; bi++;
                e.K = 2048; e.a0 = 0; e.a1 = 1;
            } else {
                e.b_is_wb = 0; e.b_row_base = si * 5 * 1024; si++;
                e.K = 1024;
                e.a0 = e.a1 = (j < 2) ? j : (j - 1);
            }
        }
        P.node_out_idx = (node < 3) ? (2 + node) : -1;
        gemm_node<<<grid, blk, DYN_SMEM>>>(P, geno, bsv, (float*)d_out);
        offset += node + 3;
    }
}